// round 2
// baseline (speedup 1.0000x reference)
#include <cuda_runtime.h>
#include <cuda_bf16.h>

#define N_BATCH 4096
#define T_SEQ   200

// ---------------- device scratch (no allocs allowed) ----------------
__device__ float g_pooled[N_BATCH * 128];          // 2 MB
// Wt1[k][t][jj] : j = t + 128*jj, jj<4   (k<128)
__device__ float g_wt1[128 * 512];
// Wt2[k][t][jj] : j = t + 128*jj, jj<2   (k<512)
__device__ float g_wt2[512 * 256];
// Wt3[k][t]     : j = t                  (k<256)
__device__ float g_wt3[256 * 128];

// ---------------- f32x2 helpers (sm_103a packed fp32) ----------------
typedef unsigned long long u64;

__device__ __forceinline__ u64 pk2(float lo, float hi) {
    u64 r; asm("mov.b64 %0, {%1,%2};" : "=l"(r) : "f"(lo), "f"(hi)); return r;
}
__device__ __forceinline__ float2 upk(u64 v) {
    float2 f; asm("mov.b64 {%0,%1}, %2;" : "=f"(f.x), "=f"(f.y) : "l"(v)); return f;
}
__device__ __forceinline__ void fma2(u64& d, u64 a, u64 b) {
    asm("fma.rn.f32x2 %0, %1, %2, %0;" : "+l"(d) : "l"(a), "l"(b));
}

// ---------------- 1) fused pool + weight transpose ----------------
// blocks [0,512)   : pooling, one warp per sequence (8 warps/block)
// blocks [512,1408): weight transpose, 256 elems/block
__global__ void prep_kernel(const int* __restrict__ x,
                            const int* __restrict__ lengths,
                            const float* __restrict__ emb,
                            const float* __restrict__ W1,
                            const float* __restrict__ W2,
                            const float* __restrict__ W3) {
    if (blockIdx.x < 512) {
        int gwarp = (blockIdx.x * 256 + threadIdx.x) >> 5;
        int lane  = threadIdx.x & 31;

        const int* xr = x + gwarp * T_SEQ;
        int len = lengths[gwarp];

        const float4* emb4 = (const float4*)emb;      // row = 32 float4
        float4 acc = make_float4(0.f, 0.f, 0.f, 0.f);

        int t = 0;
        for (; t + 4 <= len; t += 4) {
            int i0 = xr[t], i1 = xr[t + 1], i2 = xr[t + 2], i3 = xr[t + 3];
            float4 a = emb4[i0 * 32 + lane];
            float4 b = emb4[i1 * 32 + lane];
            float4 c = emb4[i2 * 32 + lane];
            float4 d = emb4[i3 * 32 + lane];
            acc.x += a.x + b.x + c.x + d.x;
            acc.y += a.y + b.y + c.y + d.y;
            acc.z += a.z + b.z + c.z + d.z;
            acc.w += a.w + b.w + c.w + d.w;
        }
        for (; t < len; ++t) {
            float4 a = emb4[xr[t] * 32 + lane];
            acc.x += a.x; acc.y += a.y; acc.z += a.z; acc.w += a.w;
        }
        float inv = 1.0f / (float)len;
        acc.x *= inv; acc.y *= inv; acc.z *= inv; acc.w *= inv;
        ((float4*)g_pooled)[gwarp * 32 + lane] = acc;
    } else {
        int idx = (blockIdx.x - 512) * 256 + threadIdx.x;
        if (idx < 65536) {
            // wt1[k*512 + t*4 + jj] = W1[(t + 128*jj)*128 + k]
            int k = idx >> 9, rem = idx & 511;
            int tt = rem >> 2, jj = rem & 3;
            g_wt1[idx] = W1[(tt + 128 * jj) * 128 + k];
        } else if (idx < 65536 + 131072) {
            int i2 = idx - 65536;
            // wt2[k*256 + t*2 + jj] = W2[(t + 128*jj)*512 + k]
            int k = i2 >> 8, rem = i2 & 255;
            int tt = rem >> 1, jj = rem & 1;
            g_wt2[i2] = W2[(tt + 128 * jj) * 512 + k];
        } else if (idx < 65536 + 131072 + 32768) {
            int i3 = idx - 65536 - 131072;
            // wt3[k*128 + t] = W3[t*256 + k]
            int k = i3 >> 7, tt = i3 & 127;
            g_wt3[i3] = W3[tt * 256 + k];
        }
    }
}

// ---------------- 2) fused MLP: 16 rows (8 f32x2 pairs) per block ----------------
// smem: A (32KB) holds layer1 out (512 f) and layer3 out (128 f)
//       B (16KB) holds staged input (128 f) and layer2 out (256 f)
// activation word at [p*F + k] = (row 2p value, row 2p+1 value)
__global__ void __launch_bounds__(128) mlp_kernel(
        const float* __restrict__ b1,
        const float* __restrict__ b2,
        const float* __restrict__ b3,
        const float* __restrict__ W4,
        const float* __restrict__ b4,
        float* __restrict__ out) {
    __shared__ __align__(16) u64 A[8 * 512];   // 32 KB
    __shared__ __align__(16) u64 B[8 * 256];   // 16 KB

    int tid = threadIdx.x;
    int r0  = blockIdx.x * 16;

    // ---- stage pooled rows into B[p*128 + k] as row pairs ----
    #pragma unroll
    for (int i = 0; i < 8; ++i) {
        int ii = i * 128 + tid;
        int p = ii >> 7, k = ii & 127;
        float lo = g_pooled[(r0 + 2 * p)     * 128 + k];
        float hi = g_pooled[(r0 + 2 * p + 1) * 128 + k];
        B[p * 128 + k] = pk2(lo, hi);
    }
    __syncthreads();

    // ---- layer 1: 128 -> 512, outputs j = tid + 128*jj, jj<4 ----
    {
        u64 acc[8][4];
        #pragma unroll
        for (int p = 0; p < 8; ++p)
            #pragma unroll
            for (int j = 0; j < 4; ++j) acc[p][j] = 0ULL;

        const float4* Wt = (const float4*)g_wt1;  // [k][tid] -> 4 j-chunks
        #pragma unroll 2
        for (int k = 0; k < 128; ++k) {
            float4 w = Wt[k * 128 + tid];
            u64 w0 = pk2(w.x, w.x), w1 = pk2(w.y, w.y);
            u64 w2 = pk2(w.z, w.z), w3 = pk2(w.w, w.w);
            #pragma unroll
            for (int p = 0; p < 8; ++p) {
                u64 a = B[p * 128 + k];            // uniform broadcast
                fma2(acc[p][0], a, w0);
                fma2(acc[p][1], a, w1);
                fma2(acc[p][2], a, w2);
                fma2(acc[p][3], a, w3);
            }
        }
        #pragma unroll
        for (int jj = 0; jj < 4; ++jj) {
            float bj = b1[tid + 128 * jj];
            #pragma unroll
            for (int p = 0; p < 8; ++p) {
                float2 v = upk(acc[p][jj]);
                v.x = fmaxf(v.x + bj, 0.f);
                v.y = fmaxf(v.y + bj, 0.f);
                A[p * 512 + tid + 128 * jj] = pk2(v.x, v.y);  // stride-1, conflict-free
            }
        }
    }
    __syncthreads();

    // ---- layer 2: 512 -> 256, outputs j = tid + 128*jj, jj<2 ----
    {
        u64 acc[8][2];
        #pragma unroll
        for (int p = 0; p < 8; ++p) { acc[p][0] = 0ULL; acc[p][1] = 0ULL; }

        const float2* Wt = (const float2*)g_wt2;  // [k][tid] -> 2 j-chunks
        #pragma unroll 4
        for (int k = 0; k < 512; ++k) {
            float2 w = Wt[k * 128 + tid];
            u64 w0 = pk2(w.x, w.x), w1 = pk2(w.y, w.y);
            #pragma unroll
            for (int p = 0; p < 8; ++p) {
                u64 a = A[p * 512 + k];
                fma2(acc[p][0], a, w0);
                fma2(acc[p][1], a, w1);
            }
        }
        #pragma unroll
        for (int jj = 0; jj < 2; ++jj) {
            float bj = b2[tid + 128 * jj];
            #pragma unroll
            for (int p = 0; p < 8; ++p) {
                float2 v = upk(acc[p][jj]);
                v.x = fmaxf(v.x + bj, 0.f);
                v.y = fmaxf(v.y + bj, 0.f);
                B[p * 256 + tid + 128 * jj] = pk2(v.x, v.y);
            }
        }
    }
    __syncthreads();

    // ---- layer 3: 256 -> 128, output j = tid ----
    {
        u64 acc[8];
        #pragma unroll
        for (int p = 0; p < 8; ++p) acc[p] = 0ULL;

        #pragma unroll 4
        for (int k = 0; k < 256; ++k) {
            float w = g_wt3[k * 128 + tid];
            u64 ws = pk2(w, w);
            #pragma unroll
            for (int p = 0; p < 8; ++p) {
                u64 a = B[p * 256 + k];
                fma2(acc[p], a, ws);
            }
        }
        float bj = b3[tid];
        #pragma unroll
        for (int p = 0; p < 8; ++p) {
            float2 v = upk(acc[p]);
            v.x = fmaxf(v.x + bj, 0.f);
            v.y = fmaxf(v.y + bj, 0.f);
            A[p * 128 + tid] = pk2(v.x, v.y);
        }
    }
    __syncthreads();

    // ---- layer 4: 128 -> 2 (one warp: r = tid>>1, j = tid&1) ----
    if (tid < 32) {
        int r = tid >> 1;          // 0..15
        int j = tid & 1;
        int p = r >> 1, h = r & 1;
        float acc = b4[j];
        #pragma unroll 4
        for (int k = 0; k < 128; ++k) {
            float2 v = upk(A[p * 128 + k]);
            acc += (h ? v.y : v.x) * W4[j * 128 + k];
        }
        out[(r0 + r) * 2 + j] = acc;
    }
}

// ---------------- launch ----------------
extern "C" void kernel_launch(void* const* d_in, const int* in_sizes, int n_in,
                              void* d_out, int out_size) {
    const int*   x       = (const int*)  d_in[0];
    const int*   lengths = (const int*)  d_in[1];
    const float* emb     = (const float*)d_in[2];
    const float* W1      = (const float*)d_in[3];
    const float* b1      = (const float*)d_in[4];
    const float* W2      = (const float*)d_in[5];
    const float* b2      = (const float*)d_in[6];
    const float* W3      = (const float*)d_in[7];
    const float* b3      = (const float*)d_in[8];
    const float* W4      = (const float*)d_in[9];
    const float* b4      = (const float*)d_in[10];
    float* out = (float*)d_out;

    // 1) pooling (512 blocks) + weight transpose (896 blocks), fused
    prep_kernel<<<1408, 256>>>(x, lengths, emb, W1, W2, W3);

    // 2) fused f32x2 MLP: 16 rows per block
    mlp_kernel<<<N_BATCH / 16, 128>>>(b1, b2, b3, W4, b4, out);
}

// round 3
// speedup vs baseline: 1.0376x; 1.0376x over previous
#include <cuda_runtime.h>
#include <cuda_bf16.h>

#define N_BATCH 4096
#define T_SEQ   200

// ---------------- device scratch (no allocs allowed) ----------------
// wt1[k*512 + t*2 + jj] = W1[(t + 256*jj)*128 + k]   (k<128, t<256, jj<2)
__device__ float g_wt1[128 * 512];
// wt2[k*256 + j] = W2[j*512 + k]                     (k<512, j<256)
__device__ float g_wt2[512 * 256];
// wt3[k*128 + j] = W3[j*256 + k]                     (k<256, j<128)
__device__ float g_wt3[256 * 128];

// ---------------- f32x2 helpers (sm_103a packed fp32) ----------------
typedef unsigned long long u64;

__device__ __forceinline__ u64 pk2(float lo, float hi) {
    u64 r; asm("mov.b64 %0, {%1,%2};" : "=l"(r) : "f"(lo), "f"(hi)); return r;
}
__device__ __forceinline__ float2 upk(u64 v) {
    float2 f; asm("mov.b64 {%0,%1}, %2;" : "=f"(f.x), "=f"(f.y) : "l"(v)); return f;
}
__device__ __forceinline__ void fma2(u64& d, u64 a, u64 b) {
    asm("fma.rn.f32x2 %0, %1, %2, %0;" : "+l"(d) : "l"(a), "l"(b));
}

// ---------------- 1) weight transpose (coalesced reads) ----------------
__global__ void transpose_kernel(const float* __restrict__ W1,
                                 const float* __restrict__ W2,
                                 const float* __restrict__ W3) {
    int idx = blockIdx.x * blockDim.x + threadIdx.x;
    if (idx < 65536) {                       // W1: 512x128
        int j = idx >> 7, k = idx & 127;
        int t = j & 255, jj = j >> 8;
        g_wt1[k * 512 + t * 2 + jj] = W1[idx];
    } else if (idx < 65536 + 131072) {       // W2: 256x512
        int i2 = idx - 65536;
        int j = i2 >> 9, k = i2 & 511;
        g_wt2[k * 256 + j] = W2[i2];
    } else if (idx < 65536 + 131072 + 32768) { // W3: 128x256
        int i3 = idx - 65536 - 131072;
        int j = i3 >> 8, k = i3 & 255;
        g_wt3[k * 128 + j] = W3[i3];
    }
}

// ---------------- 2) fused pool + MLP: 16 rows per block, 256 threads ----------------
// smem A (32KB): layer1 out [p][n1] (n1<512) and layer3 out [p][j] (j<128)
// smem B (16KB): pooled input [p][k] (k<128), then layer2 out [p][j] (j<256)
// activation u64 word = (row 2p value, row 2p+1 value)
__global__ void __launch_bounds__(256) mlp_kernel(
        const int*   __restrict__ x,
        const int*   __restrict__ lengths,
        const float* __restrict__ emb,
        const float* __restrict__ b1,
        const float* __restrict__ b2,
        const float* __restrict__ b3,
        const float* __restrict__ W4,
        const float* __restrict__ b4,
        float* __restrict__ out) {
    __shared__ __align__(16) u64 A[8 * 512];   // 32 KB
    __shared__ __align__(16) u64 B[8 * 256];   // 16 KB

    int tid  = threadIdx.x;
    int w    = tid >> 5;          // warp 0..7  == pair p
    int lane = tid & 31;
    int r0   = blockIdx.x * 16;

    // ---- pooling: warp w pools rows r0+2w (lo) and r0+2w+1 (hi) ----
    {
        const float4* emb4 = (const float4*)emb;
        float4 accs[2];
        #pragma unroll
        for (int s = 0; s < 2; ++s) {
            int row = r0 + 2 * w + s;
            const int* xr = x + row * T_SEQ;
            int len = lengths[row];
            float4 acc = make_float4(0.f, 0.f, 0.f, 0.f);
            int t = 0;
            for (; t + 4 <= len; t += 4) {
                int i0 = xr[t], i1 = xr[t + 1], i2 = xr[t + 2], i3 = xr[t + 3];
                float4 a = emb4[i0 * 32 + lane];
                float4 b = emb4[i1 * 32 + lane];
                float4 c = emb4[i2 * 32 + lane];
                float4 d = emb4[i3 * 32 + lane];
                acc.x += a.x + b.x + c.x + d.x;
                acc.y += a.y + b.y + c.y + d.y;
                acc.z += a.z + b.z + c.z + d.z;
                acc.w += a.w + b.w + c.w + d.w;
            }
            for (; t < len; ++t) {
                float4 a = emb4[xr[t] * 32 + lane];
                acc.x += a.x; acc.y += a.y; acc.z += a.z; acc.w += a.w;
            }
            float inv = 1.0f / (float)len;
            acc.x *= inv; acc.y *= inv; acc.z *= inv; acc.w *= inv;
            accs[s] = acc;
        }
        // pack into B[w*128 + k], lane owns k = 4*lane..4*lane+3
        B[w * 128 + 4 * lane + 0] = pk2(accs[0].x, accs[1].x);
        B[w * 128 + 4 * lane + 1] = pk2(accs[0].y, accs[1].y);
        B[w * 128 + 4 * lane + 2] = pk2(accs[0].z, accs[1].z);
        B[w * 128 + 4 * lane + 3] = pk2(accs[0].w, accs[1].w);
    }
    __syncthreads();

    // ---- layer 1: 128 -> 512; thread outputs j = tid + 256*jj, jj<2 ----
    {
        u64 acc[8][2];
        #pragma unroll
        for (int p = 0; p < 8; ++p) { acc[p][0] = 0ULL; acc[p][1] = 0ULL; }

        const float2* Wt = (const float2*)g_wt1;   // [k][t] -> (jj0, jj1)
        #pragma unroll 2
        for (int k = 0; k < 128; ++k) {
            float2 wv = Wt[k * 256 + tid];
            u64 w0 = pk2(wv.x, wv.x), w1 = pk2(wv.y, wv.y);
            #pragma unroll
            for (int p = 0; p < 8; ++p) {
                u64 a = B[p * 128 + k];            // uniform broadcast
                fma2(acc[p][0], a, w0);
                fma2(acc[p][1], a, w1);
            }
        }
        #pragma unroll
        for (int jj = 0; jj < 2; ++jj) {
            float bj = b1[tid + 256 * jj];
            #pragma unroll
            for (int p = 0; p < 8; ++p) {
                float2 v = upk(acc[p][jj]);
                v.x = fmaxf(v.x + bj, 0.f);
                v.y = fmaxf(v.y + bj, 0.f);
                // n1 = tid + 256*jj  ->  slot jj*256 + tid == n1
                A[p * 512 + jj * 256 + tid] = pk2(v.x, v.y);
            }
        }
    }
    __syncthreads();

    // ---- layer 2: 512 -> 256; thread output j = tid ----
    {
        u64 acc[8];
        #pragma unroll
        for (int p = 0; p < 8; ++p) acc[p] = 0ULL;

        #pragma unroll 4
        for (int k = 0; k < 512; ++k) {
            float wv = g_wt2[k * 256 + tid];       // coalesced
            u64 ws = pk2(wv, wv);
            #pragma unroll
            for (int p = 0; p < 8; ++p) {
                u64 a = A[p * 512 + k];            // uniform broadcast
                fma2(acc[p], a, ws);
            }
        }
        float bj = b2[tid];
        #pragma unroll
        for (int p = 0; p < 8; ++p) {
            float2 v = upk(acc[p]);
            v.x = fmaxf(v.x + bj, 0.f);
            v.y = fmaxf(v.y + bj, 0.f);
            B[p * 256 + tid] = pk2(v.x, v.y);
        }
    }
    __syncthreads();

    // ---- layer 3: 256 -> 128; j = tid&127, p-range split by tid>>7 ----
    {
        int j    = tid & 127;
        int pbase = (tid >> 7) * 4;                // 0 or 4
        u64 acc[4];
        #pragma unroll
        for (int q = 0; q < 4; ++q) acc[q] = 0ULL;

        #pragma unroll 4
        for (int k = 0; k < 256; ++k) {
            float wv = g_wt3[k * 128 + j];         // coalesced
            u64 ws = pk2(wv, wv);
            #pragma unroll
            for (int q = 0; q < 4; ++q) {
                u64 a = B[(pbase + q) * 256 + k];  // uniform broadcast
                fma2(acc[q], a, ws);
            }
        }
        float bj = b3[j];
        #pragma unroll
        for (int q = 0; q < 4; ++q) {
            float2 v = upk(acc[q]);
            v.x = fmaxf(v.x + bj, 0.f);
            v.y = fmaxf(v.y + bj, 0.f);
            A[(pbase + q) * 128 + j] = pk2(v.x, v.y);
        }
    }
    __syncthreads();

    // ---- layer 4: 128 -> 2 (one warp: r = tid>>1, jo = tid&1) ----
    if (tid < 32) {
        int r = tid >> 1;              // 0..15
        int jo = tid & 1;
        int p = r >> 1, h = r & 1;
        float acc = b4[jo];
        #pragma unroll 4
        for (int k = 0; k < 128; ++k) {
            float2 v = upk(A[p * 128 + k]);
            acc += (h ? v.y : v.x) * W4[jo * 128 + k];
        }
        out[(r0 + r) * 2 + jo] = acc;
    }
}

// ---------------- launch ----------------
extern "C" void kernel_launch(void* const* d_in, const int* in_sizes, int n_in,
                              void* d_out, int out_size) {
    const int*   x       = (const int*)  d_in[0];
    const int*   lengths = (const int*)  d_in[1];
    const float* emb     = (const float*)d_in[2];
    const float* W1      = (const float*)d_in[3];
    const float* b1      = (const float*)d_in[4];
    const float* W2      = (const float*)d_in[5];
    const float* b2      = (const float*)d_in[6];
    const float* W3      = (const float*)d_in[7];
    const float* b3      = (const float*)d_in[8];
    const float* W4      = (const float*)d_in[9];
    const float* b4      = (const float*)d_in[10];
    float* out = (float*)d_out;

    // 1) weight transpose (229376 elems, coalesced reads)
    transpose_kernel<<<(229376 + 255) / 256, 256>>>(W1, W2, W3);

    // 2) fused pool + f32x2 MLP: 16 rows per block
    mlp_kernel<<<N_BATCH / 16, 256>>>(x, lengths, emb, b1, b2, b3, W4, b4, out);
}